// round 1
// baseline (speedup 1.0000x reference)
#include <cuda_runtime.h>
#include <cuda_bf16.h>

typedef unsigned long long u64;
#define T_LEN 1024
#define NOUT 10

// ---- packed f32x2 helpers (Blackwell dual-FP32 path) ----
static __device__ __forceinline__ u64 pk2(float lo, float hi) {
    u64 r; asm("mov.b64 %0, {%1, %2};" : "=l"(r) : "f"(lo), "f"(hi)); return r;
}
static __device__ __forceinline__ void upk2(u64 v, float& lo, float& hi) {
    asm("mov.b64 {%0, %1}, %2;" : "=f"(lo), "=f"(hi) : "l"(v));
}
static __device__ __forceinline__ u64 ffma2(u64 a, u64 b, u64 c) {
    u64 d; asm("fma.rn.f32x2 %0, %1, %2, %3;" : "=l"(d) : "l"(a), "l"(b), "l"(c)); return d;
}
static __device__ __forceinline__ u64 fmul2(u64 a, u64 b) {
    u64 d; asm("mul.rn.f32x2 %0, %1, %2;" : "=l"(d) : "l"(a), "l"(b)); return d;
}

// One warp = 2 batch rows. lane k owns output/state component k of both rows.
// W columns (paired over the reduction index i) live in 64 registers per lane.
// State exchanged through SMEM double buffer (broadcast LDS.128 reads).
__global__ void __launch_bounds__(64, 7)
tt_kernel(const float* __restrict__ x, const float* __restrict__ Wf,
          const float* __restrict__ Ws, const float* __restrict__ Wl,
          float* __restrict__ out, int batch)
{
    __shared__ __align__(16) float sb[2][2][2][32];   // [warp][buf][row][comp]
    __shared__ float zb[2][2][NOUT];
    const int lane = threadIdx.x & 31;
    const int w    = threadIdx.x >> 5;
    const int gw   = blockIdx.x * 2 + w;
    const int b0   = gw * 2;
    const int b1   = b0 + 1;
    if (b0 >= batch) return;

    // W_shared is (32, 2, 32): elem [i][j][k] at i*64 + j*32 + k.
    // w0[p] = (W[2p][0][k], W[2p+1][0][k]);  w1[p] = same with j=1.
    u64 w0[16], w1[16];
#pragma unroll
    for (int p = 0; p < 16; ++p) {
        w0[p] = pk2(Ws[(2*p)*64 +      lane], Ws[(2*p+1)*64 +      lane]);
        w1[p] = pk2(Ws[(2*p)*64 + 32 + lane], Ws[(2*p+1)*64 + 32 + lane]);
    }

    // init state: sum over j of W_first[0][j][k]  (pad==1, state==1)
    const float sinit = Wf[lane] + Wf[32 + lane];
    float* st0 = &sb[w][0][0][0];
    float* st1 = &sb[w][1][0][0];
    st0[lane]      = sinit;
    st0[32 + lane] = sinit;

    const float* xA = x + (size_t)b0 * T_LEN;
    const float* xB = x + (size_t)b1 * T_LEN;

    // feature chunk: lane t' holds (cos,sin)(pi/2 * x[b, base+t']); broadcast per step.
    float cA, snA, cB, snB;
    sincospif(0.5f * xA[lane], &snA, &cA);
    sincospif(0.5f * xB[lane], &snB, &cB);
    __syncwarp();

    const float* rd = st0;
    float*       wr = st1;
    float lastA = sinit, lastB = sinit;

    for (int base = 0; base < T_LEN; base += 32) {
        // prefetch next 32 inputs (latency hidden across the 32-step chunk)
        float nxa = 0.f, nxb = 0.f;
        if (base + 32 < T_LEN) {
            nxa = xA[base + 32 + lane];
            nxb = xB[base + 32 + lane];
        }
#pragma unroll 4
        for (int tt = 0; tt < 32; ++tt) {
            const float ca  = __shfl_sync(0xffffffffu, cA,  tt);
            const float sa  = __shfl_sync(0xffffffffu, snA, tt);
            const float cb  = __shfl_sync(0xffffffffu, cB,  tt);
            const float sbv = __shfl_sync(0xffffffffu, snB, tt);

            const float4* sA4 = (const float4*)rd;         // row b0 state
            const float4* sB4 = (const float4*)(rd + 32);  // row b1 state

            float4 va = sA4[0];
            float4 vb = sB4[0];
            u64 pa0 = pk2(va.x, va.y), pa1 = pk2(va.z, va.w);
            u64 pb0 = pk2(vb.x, vb.y), pb1 = pk2(vb.z, vb.w);
            u64 accA0 = fmul2(pa0, w0[0]);
            u64 accA1 = fmul2(pa0, w1[0]);
            u64 accB0 = fmul2(pb0, w0[0]);
            u64 accB1 = fmul2(pb0, w1[0]);
            accA0 = ffma2(pa1, w0[1], accA0);
            accA1 = ffma2(pa1, w1[1], accA1);
            accB0 = ffma2(pb1, w0[1], accB0);
            accB1 = ffma2(pb1, w1[1], accB1);
#pragma unroll
            for (int q = 1; q < 8; ++q) {
                va = sA4[q];
                vb = sB4[q];
                pa0 = pk2(va.x, va.y); pa1 = pk2(va.z, va.w);
                pb0 = pk2(vb.x, vb.y); pb1 = pk2(vb.z, vb.w);
                accA0 = ffma2(pa0, w0[2*q],   accA0);
                accA1 = ffma2(pa0, w1[2*q],   accA1);
                accB0 = ffma2(pb0, w0[2*q],   accB0);
                accB1 = ffma2(pb0, w1[2*q],   accB1);
                accA0 = ffma2(pa1, w0[2*q+1], accA0);
                accA1 = ffma2(pa1, w1[2*q+1], accA1);
                accB0 = ffma2(pb1, w0[2*q+1], accB0);
                accB1 = ffma2(pb1, w1[2*q+1], accB1);
            }
            float l0, h0, l1, h1;
            upk2(accA0, l0, h0); upk2(accA1, l1, h1);
            lastA = ca * (l0 + h0) + sa * (l1 + h1);
            upk2(accB0, l0, h0); upk2(accB1, l1, h1);
            lastB = cb * (l0 + h0) + sbv * (l1 + h1);

            wr[lane]      = lastA;
            wr[32 + lane] = lastB;
            float* tmp = wr; wr = (float*)rd; rd = tmp;
            __syncwarp();
        }
        // zero is a fixed point of the recurrence: once the state vector is
        // exactly 0 (fp32 underflow of the contracting scan), all remaining
        // steps are identity. Deterministic (input-dependent) early exit,
        // bit-identical to running the loop to completion.
        if (__ballot_sync(0xffffffffu, (lastA != 0.f) || (lastB != 0.f)) == 0u)
            break;
        sincospif(0.5f * nxa, &snA, &cA);
        sincospif(0.5f * nxb, &snB, &cB);
    }
    __syncwarp();

    // readout: z[n] = sum_i state[i] * (W_last[i][0][n] + W_last[i][1][n])
    // W_last is (32, 2, 10): elem [i][j][n] at i*20 + j*10 + n.
    const int n   = lane & 15;
    const int grp = lane >> 4;   // 0 -> b0, 1 -> b1
    if (n < NOUT) {
        float acc = 0.f;
#pragma unroll
        for (int i = 0; i < 32; ++i) {
            float wv = Wl[i*20 + n] + Wl[i*20 + 10 + n];
            acc = fmaf(rd[grp*32 + i], wv, acc);
        }
        zb[w][grp][n] = acc;
    }
    __syncwarp();
    if (n < NOUT) {
        float m = -3.402823466e38f;
#pragma unroll
        for (int j = 0; j < NOUT; ++j) m = fmaxf(m, zb[w][grp][j]);
        float s = 0.f;
#pragma unroll
        for (int j = 0; j < NOUT; ++j) s += expf(zb[w][grp][j] - m);
        const int b = grp ? b1 : b0;
        out[b * NOUT + n] = zb[w][grp][n] - m - logf(s);
    }
}

extern "C" void kernel_launch(void* const* d_in, const int* in_sizes, int n_in,
                              void* d_out, int out_size)
{
    const float* x  = (const float*)d_in[0];   // tensor  (batch, 1024)
    const float* Wf = (const float*)d_in[1];   // W_first (1, 2, 32)
    const float* Ws = (const float*)d_in[2];   // W_shared(32, 2, 32)
    const float* Wl = (const float*)d_in[3];   // W_last  (32, 2, 10)
    float* out = (float*)d_out;                // (batch, 10) float32

    int batch  = in_sizes[0] / T_LEN;          // 4096
    int warps  = (batch + 1) / 2;              // 2 rows per warp
    int blocks = (warps + 1) / 2;              // 2 warps (64 threads) per CTA

    tt_kernel<<<blocks, 64>>>(x, Wf, Ws, Wl, out, batch);
}

// round 2
// speedup vs baseline: 1.1954x; 1.1954x over previous
#include <cuda_runtime.h>
#include <cuda_bf16.h>

typedef unsigned long long u64;
typedef unsigned int u32;
#define T_LEN 1024
#define NOUT 10

// ---- packed f32x2 helpers (Blackwell dual-FP32 path) ----
static __device__ __forceinline__ u64 pk2(float lo, float hi) {
    u64 r; asm("mov.b64 %0, {%1, %2};" : "=l"(r) : "f"(lo), "f"(hi)); return r;
}
static __device__ __forceinline__ void upk2(u64 v, float& lo, float& hi) {
    asm("mov.b64 {%0, %1}, %2;" : "=f"(lo), "=f"(hi) : "l"(v));
}
static __device__ __forceinline__ u64 ffma2(u64 a, u64 b, u64 c) {
    u64 d; asm("fma.rn.f32x2 %0, %1, %2, %3;" : "=l"(d) : "l"(a), "l"(b), "l"(c)); return d;
}
static __device__ __forceinline__ u64 fmul2(u64 a, u64 b) {
    u64 d; asm("mul.rn.f32x2 %0, %1, %2;" : "=l"(d) : "l"(a), "l"(b)); return d;
}
static __device__ __forceinline__ u64 fadd2(u64 a, u64 b) {
    u64 d; asm("add.rn.f32x2 %0, %1, %2;" : "=l"(d) : "l"(a), "l"(b)); return d;
}
// 16B shared load delivering two packed f32x2 operands directly (no repack MOVs)
static __device__ __forceinline__ void lds_v2(u64& a, u64& b, u32 addr) {
    asm volatile("ld.shared.v2.b64 {%0, %1}, [%2];" : "=l"(a), "=l"(b) : "r"(addr));
}

// One warp = 2 batch rows. Lane k owns state component k of both rows.
// W_shared columns (paired over reduction index i) live in 64 registers/lane.
// State exchanged through a SMEM double buffer; per-step features read as one
// broadcast LDS.128 from a per-chunk SMEM table.
__global__ void __launch_bounds__(64, 7)
tt_kernel(const float* __restrict__ x, const float* __restrict__ Wf,
          const float* __restrict__ Ws, const float* __restrict__ Wl,
          float* __restrict__ out, int batch)
{
    __shared__ __align__(16) float sb[2][2][64];   // [warp][buf][row*32+comp]
    __shared__ __align__(16) float ft[2][32][4];   // [warp][t][{cA,sA,cB,sB}]
    __shared__ float zb[2][2][NOUT];
    const int lane = threadIdx.x & 31;
    const int w    = threadIdx.x >> 5;
    const int gw   = blockIdx.x * 2 + w;
    const int b0   = gw * 2;
    const int b1   = b0 + 1;
    if (b0 >= batch) return;

    // W_shared is (32, 2, 32): elem [i][j][k] at i*64 + j*32 + k.
    // w0[p] = (W[2p][0][k], W[2p+1][0][k]);  w1[p] = same with j=1.
    u64 w0[16], w1[16];
#pragma unroll
    for (int p = 0; p < 16; ++p) {
        w0[p] = pk2(Ws[(2*p)*64 +      lane], Ws[(2*p+1)*64 +      lane]);
        w1[p] = pk2(Ws[(2*p)*64 + 32 + lane], Ws[(2*p+1)*64 + 32 + lane]);
    }

    // init state: sum over j of W_first[0][j][k]  (pad==1, state==1)
    const float sinit = Wf[lane] + Wf[32 + lane];
    sb[w][0][lane]      = sinit;
    sb[w][0][32 + lane] = sinit;

    const u32 buf0 = (u32)__cvta_generic_to_shared(&sb[w][0][0]);
    const u32 buf1 = (u32)__cvta_generic_to_shared(&sb[w][1][0]);

    const float* xA = x + (size_t)b0 * T_LEN;
    const float* xB = x + (size_t)b1 * T_LEN;

    // first chunk's features: lane t' holds (cos,sin) of both rows at t=base+t'
    {
        float c, s;
        sincospif(0.5f * xA[lane], &s, &c); ft[w][lane][0] = c; ft[w][lane][1] = s;
        sincospif(0.5f * xB[lane], &s, &c); ft[w][lane][2] = c; ft[w][lane][3] = s;
    }
    __syncwarp();

    u32 rd = buf0, wr = buf1;
    float* rdp = &sb[w][0][0];
    float* wrp = &sb[w][1][0];
    float lastA = sinit, lastB = sinit;
    bool alive = true;

    for (int base = 0; base < T_LEN && alive; base += 32) {
        // prefetch next 32 inputs (global latency hidden across the chunk)
        float nxa = 0.f, nxb = 0.f;
        if (base + 32 < T_LEN) {
            nxa = xA[base + 32 + lane];
            nxb = xB[base + 32 + lane];
        }
        for (int blk = 0; blk < 4 && alive; ++blk) {
#pragma unroll
            for (int k8 = 0; k8 < 8; ++k8) {
                const int tt = blk * 8 + k8;
                u64 a0, a1, a2, a3;
                u64 m0a, m0b, m1a, m1b;   // row A: W0/W1, split chains (depth 8)
                u64 n0a, n0b, n1a, n1b;   // row B

                // ---- row A, pairs 0..7 ----
                lds_v2(a0, a1, rd);
                lds_v2(a2, a3, rd + 16);
                m0a = fmul2(a0, w0[0]);        m1a = fmul2(a0, w1[0]);
                m0a = ffma2(a1, w0[1], m0a);   m1a = ffma2(a1, w1[1], m1a);
                m0a = ffma2(a2, w0[2], m0a);   m1a = ffma2(a2, w1[2], m1a);
                m0a = ffma2(a3, w0[3], m0a);   m1a = ffma2(a3, w1[3], m1a);
                lds_v2(a0, a1, rd + 32);
                lds_v2(a2, a3, rd + 48);
                m0a = ffma2(a0, w0[4], m0a);   m1a = ffma2(a0, w1[4], m1a);
                m0a = ffma2(a1, w0[5], m0a);   m1a = ffma2(a1, w1[5], m1a);
                m0a = ffma2(a2, w0[6], m0a);   m1a = ffma2(a2, w1[6], m1a);
                m0a = ffma2(a3, w0[7], m0a);   m1a = ffma2(a3, w1[7], m1a);
                // ---- row A, pairs 8..15 (second chain) ----
                lds_v2(a0, a1, rd + 64);
                lds_v2(a2, a3, rd + 80);
                m0b = fmul2(a0, w0[8]);        m1b = fmul2(a0, w1[8]);
                m0b = ffma2(a1, w0[9],  m0b);  m1b = ffma2(a1, w1[9],  m1b);
                m0b = ffma2(a2, w0[10], m0b);  m1b = ffma2(a2, w1[10], m1b);
                m0b = ffma2(a3, w0[11], m0b);  m1b = ffma2(a3, w1[11], m1b);
                lds_v2(a0, a1, rd + 96);
                lds_v2(a2, a3, rd + 112);
                m0b = ffma2(a0, w0[12], m0b);  m1b = ffma2(a0, w1[12], m1b);
                m0b = ffma2(a1, w0[13], m0b);  m1b = ffma2(a1, w1[13], m1b);
                m0b = ffma2(a2, w0[14], m0b);  m1b = ffma2(a2, w1[14], m1b);
                m0b = ffma2(a3, w0[15], m0b);  m1b = ffma2(a3, w1[15], m1b);
                // ---- row B, pairs 0..7 ----
                lds_v2(a0, a1, rd + 128);
                lds_v2(a2, a3, rd + 144);
                n0a = fmul2(a0, w0[0]);        n1a = fmul2(a0, w1[0]);
                n0a = ffma2(a1, w0[1], n0a);   n1a = ffma2(a1, w1[1], n1a);
                n0a = ffma2(a2, w0[2], n0a);   n1a = ffma2(a2, w1[2], n1a);
                n0a = ffma2(a3, w0[3], n0a);   n1a = ffma2(a3, w1[3], n1a);
                lds_v2(a0, a1, rd + 160);
                lds_v2(a2, a3, rd + 176);
                n0a = ffma2(a0, w0[4], n0a);   n1a = ffma2(a0, w1[4], n1a);
                n0a = ffma2(a1, w0[5], n0a);   n1a = ffma2(a1, w1[5], n1a);
                n0a = ffma2(a2, w0[6], n0a);   n1a = ffma2(a2, w1[6], n1a);
                n0a = ffma2(a3, w0[7], n0a);   n1a = ffma2(a3, w1[7], n1a);
                // ---- row B, pairs 8..15 ----
                lds_v2(a0, a1, rd + 192);
                lds_v2(a2, a3, rd + 208);
                n0b = fmul2(a0, w0[8]);        n1b = fmul2(a0, w1[8]);
                n0b = ffma2(a1, w0[9],  n0b);  n1b = ffma2(a1, w1[9],  n1b);
                n0b = ffma2(a2, w0[10], n0b);  n1b = ffma2(a2, w1[10], n1b);
                n0b = ffma2(a3, w0[11], n0b);  n1b = ffma2(a3, w1[11], n1b);
                lds_v2(a0, a1, rd + 224);
                lds_v2(a2, a3, rd + 240);
                n0b = ffma2(a0, w0[12], n0b);  n1b = ffma2(a0, w1[12], n1b);
                n0b = ffma2(a1, w0[13], n0b);  n1b = ffma2(a1, w1[13], n1b);
                n0b = ffma2(a2, w0[14], n0b);  n1b = ffma2(a2, w1[14], n1b);
                n0b = ffma2(a3, w0[15], n0b);  n1b = ffma2(a3, w1[15], n1b);

                // combine + feature multiply (one broadcast LDS.128)
                const float4 f = *(const float4*)&ft[w][tt][0];
                float lo, hi, t0, t1;
                u64 s0 = fadd2(m0a, m0b);
                u64 s1 = fadd2(m1a, m1b);
                upk2(s0, lo, hi); t0 = lo + hi;
                upk2(s1, lo, hi); t1 = lo + hi;
                lastA = fmaf(f.y, t1, f.x * t0);
                s0 = fadd2(n0a, n0b);
                s1 = fadd2(n1a, n1b);
                upk2(s0, lo, hi); t0 = lo + hi;
                upk2(s1, lo, hi); t1 = lo + hi;
                lastB = fmaf(f.w, t1, f.z * t0);

                wrp[lane]      = lastA;
                wrp[32 + lane] = lastB;
                { u32 t = rd; rd = wr; wr = t; }
                { float* t = rdp; rdp = wrp; wrp = t; }
                __syncwarp();
            }
            // zero is a fixed point: once the fp32 state underflows to exactly 0
            // (contracting scan), all remaining steps are identity. Deterministic,
            // bit-identical early exit, checked every 8 steps.
            if (__ballot_sync(0xffffffffu, (lastA != 0.f) || (lastB != 0.f)) == 0u)
                alive = false;
        }
        if (alive && base + 32 < T_LEN) {
            float c, s;
            sincospif(0.5f * nxa, &s, &c); ft[w][lane][0] = c; ft[w][lane][1] = s;
            sincospif(0.5f * nxb, &s, &c); ft[w][lane][2] = c; ft[w][lane][3] = s;
            __syncwarp();
        }
    }
    __syncwarp();

    // readout: z[n] = sum_i state[i] * (W_last[i][0][n] + W_last[i][1][n])
    // W_last is (32, 2, 10): elem [i][j][n] at i*20 + j*10 + n.
    const int n   = lane & 15;
    const int grp = lane >> 4;   // 0 -> b0, 1 -> b1
    if (n < NOUT) {
        float acc = 0.f;
#pragma unroll
        for (int i = 0; i < 32; ++i) {
            float wv = Wl[i*20 + n] + Wl[i*20 + 10 + n];
            acc = fmaf(rdp[grp*32 + i], wv, acc);
        }
        zb[w][grp][n] = acc;
    }
    __syncwarp();
    if (n < NOUT) {
        float m = -3.402823466e38f;
#pragma unroll
        for (int j = 0; j < NOUT; ++j) m = fmaxf(m, zb[w][grp][j]);
        float s = 0.f;
#pragma unroll
        for (int j = 0; j < NOUT; ++j) s += expf(zb[w][grp][j] - m);
        const int b = grp ? b1 : b0;
        out[b * NOUT + n] = zb[w][grp][n] - m - logf(s);
    }
}

extern "C" void kernel_launch(void* const* d_in, const int* in_sizes, int n_in,
                              void* d_out, int out_size)
{
    const float* x  = (const float*)d_in[0];   // tensor  (batch, 1024)
    const float* Wf = (const float*)d_in[1];   // W_first (1, 2, 32)
    const float* Ws = (const float*)d_in[2];   // W_shared(32, 2, 32)
    const float* Wl = (const float*)d_in[3];   // W_last  (32, 2, 10)
    float* out = (float*)d_out;                // (batch, 10) float32

    int batch  = in_sizes[0] / T_LEN;          // 4096
    int warps  = (batch + 1) / 2;              // 2 rows per warp
    int blocks = (warps + 1) / 2;              // 2 warps (64 threads) per CTA

    tt_kernel<<<blocks, 64>>>(x, Wf, Ws, Wl, out, batch);
}

// round 3
// speedup vs baseline: 1.2575x; 1.0520x over previous
#include <cuda_runtime.h>
#include <cuda_bf16.h>

typedef unsigned long long u64;
typedef unsigned int u32;
#define T_LEN 1024
#define NOUT 10

// ---- packed f32x2 helpers (Blackwell dual-FP32 path) ----
static __device__ __forceinline__ u64 pk2(float lo, float hi) {
    u64 r; asm("mov.b64 %0, {%1, %2};" : "=l"(r) : "f"(lo), "f"(hi)); return r;
}
static __device__ __forceinline__ void upk2(u64 v, float& lo, float& hi) {
    asm("mov.b64 {%0, %1}, %2;" : "=f"(lo), "=f"(hi) : "l"(v));
}
static __device__ __forceinline__ u64 ffma2(u64 a, u64 b, u64 c) {
    u64 d; asm("fma.rn.f32x2 %0, %1, %2, %3;" : "=l"(d) : "l"(a), "l"(b), "l"(c)); return d;
}
static __device__ __forceinline__ u64 fmul2(u64 a, u64 b) {
    u64 d; asm("mul.rn.f32x2 %0, %1, %2;" : "=l"(d) : "l"(a), "l"(b)); return d;
}
static __device__ __forceinline__ u64 fadd2(u64 a, u64 b) {
    u64 d; asm("add.rn.f32x2 %0, %1, %2;" : "=l"(d) : "l"(a), "l"(b)); return d;
}
// 16B shared load delivering two packed f32x2 operands directly (no repack MOVs)
static __device__ __forceinline__ void lds_v2(u64& a, u64& b, u32 addr) {
    asm volatile("ld.shared.v2.b64 {%0, %1}, [%2];" : "=l"(a), "=l"(b) : "r"(addr));
}

// ONE warp = ONE batch row. Lane k owns state component k.
// W_shared columns (paired over reduction index i) live in 64 registers/lane.
// State ping-pongs through a 2x32-float SMEM buffer (broadcast LDS.128 reads);
// per-step features come from a per-chunk SMEM float2 table.
// More resident warps (vs 2 rows/warp) hide the step-recurrence latency;
// early exit is now per-row instead of per-row-pair.
__global__ void __launch_bounds__(64, 8)
tt_kernel(const float* __restrict__ x, const float* __restrict__ Wf,
          const float* __restrict__ Ws, const float* __restrict__ Wl,
          float* __restrict__ out, int batch)
{
    __shared__ __align__(16) float  sb[2][2][32];   // [warp][buf][comp]
    __shared__ __align__(8)  float2 ft[2][32];      // [warp][t] = (cos, sin)
    __shared__ float zb[2][NOUT];
    const int lane = threadIdx.x & 31;
    const int w    = threadIdx.x >> 5;
    const int b    = blockIdx.x * 2 + w;
    if (b >= batch) return;

    // W_shared is (32, 2, 32): elem [i][j][k] at i*64 + j*32 + k.
    // w0[p] = (W[2p][0][k], W[2p+1][0][k]);  w1[p] = same with j=1.
    u64 w0[16], w1[16];
#pragma unroll
    for (int p = 0; p < 16; ++p) {
        w0[p] = pk2(Ws[(2*p)*64 +      lane], Ws[(2*p+1)*64 +      lane]);
        w1[p] = pk2(Ws[(2*p)*64 + 32 + lane], Ws[(2*p+1)*64 + 32 + lane]);
    }

    // init state: sum over j of W_first[0][j][k]  (pad==1, state==1)
    const float sinit = Wf[lane] + Wf[32 + lane];
    sb[w][0][lane] = sinit;

    const u32 buf0 = (u32)__cvta_generic_to_shared(&sb[w][0][0]);
    const u32 buf1 = (u32)__cvta_generic_to_shared(&sb[w][1][0]);

    const float* xr = x + (size_t)b * T_LEN;

    // first chunk's features: lane t' holds (cos,sin)(pi/2 * x[b, t'])
    {
        float c, s;
        sincospif(0.5f * xr[lane], &s, &c);
        ft[w][lane] = make_float2(c, s);
    }
    __syncwarp();

    u32 rd = buf0, wr = buf1;
    float* rdp = &sb[w][0][0];
    float* wrp = &sb[w][1][0];
    float last = sinit;
    bool alive = true;

    for (int base = 0; base < T_LEN && alive; base += 32) {
        // prefetch next 32 inputs (global latency hidden across the chunk)
        float nx = 0.f;
        if (base + 32 < T_LEN) nx = xr[base + 32 + lane];

        for (int blk = 0; blk < 4 && alive; ++blk) {
#pragma unroll
            for (int k8 = 0; k8 < 8; ++k8) {
                const int tt = blk * 8 + k8;
                const float2 f = ft[w][tt];     // broadcast, independent of state

                u64 a0, a1, a2, a3;
                u64 m0a, m0b, m1a, m1b;        // W0/W1, split chains (depth 8)

                // pairs 0..7 -> chain a
                lds_v2(a0, a1, rd);
                lds_v2(a2, a3, rd + 16);
                m0a = fmul2(a0, w0[0]);        m1a = fmul2(a0, w1[0]);
                m0a = ffma2(a1, w0[1], m0a);   m1a = ffma2(a1, w1[1], m1a);
                m0a = ffma2(a2, w0[2], m0a);   m1a = ffma2(a2, w1[2], m1a);
                m0a = ffma2(a3, w0[3], m0a);   m1a = ffma2(a3, w1[3], m1a);
                lds_v2(a0, a1, rd + 32);
                lds_v2(a2, a3, rd + 48);
                m0a = ffma2(a0, w0[4], m0a);   m1a = ffma2(a0, w1[4], m1a);
                m0a = ffma2(a1, w0[5], m0a);   m1a = ffma2(a1, w1[5], m1a);
                m0a = ffma2(a2, w0[6], m0a);   m1a = ffma2(a2, w1[6], m1a);
                m0a = ffma2(a3, w0[7], m0a);   m1a = ffma2(a3, w1[7], m1a);
                // pairs 8..15 -> chain b
                lds_v2(a0, a1, rd + 64);
                lds_v2(a2, a3, rd + 80);
                m0b = fmul2(a0, w0[8]);        m1b = fmul2(a0, w1[8]);
                m0b = ffma2(a1, w0[9],  m0b);  m1b = ffma2(a1, w1[9],  m1b);
                m0b = ffma2(a2, w0[10], m0b);  m1b = ffma2(a2, w1[10], m1b);
                m0b = ffma2(a3, w0[11], m0b);  m1b = ffma2(a3, w1[11], m1b);
                lds_v2(a0, a1, rd + 96);
                lds_v2(a2, a3, rd + 112);
                m0b = ffma2(a0, w0[12], m0b);  m1b = ffma2(a0, w1[12], m1b);
                m0b = ffma2(a1, w0[13], m0b);  m1b = ffma2(a1, w1[13], m1b);
                m0b = ffma2(a2, w0[14], m0b);  m1b = ffma2(a2, w1[14], m1b);
                m0b = ffma2(a3, w0[15], m0b);  m1b = ffma2(a3, w1[15], m1b);

                // combine + feature multiply
                float lo, hi, t0, t1;
                u64 s0 = fadd2(m0a, m0b);
                u64 s1 = fadd2(m1a, m1b);
                upk2(s0, lo, hi); t0 = lo + hi;
                upk2(s1, lo, hi); t1 = lo + hi;
                last = fmaf(f.y, t1, f.x * t0);

                wrp[lane] = last;
                { u32 t = rd; rd = wr; wr = t; }
                { float* t = rdp; rdp = wrp; wrp = t; }
                __syncwarp();
            }
            // zero is a fixed point: once the fp32 state underflows to exactly 0
            // (contracting scan), remaining steps are identity. Deterministic,
            // bit-identical early exit, checked every 8 steps, PER ROW.
            if (__ballot_sync(0xffffffffu, last != 0.f) == 0u)
                alive = false;
        }
        if (alive && base + 32 < T_LEN) {
            float c, s;
            sincospif(0.5f * nx, &s, &c);
            ft[w][lane] = make_float2(c, s);
            __syncwarp();
        }
    }
    __syncwarp();

    // readout: z[n] = sum_i state[i] * (W_last[i][0][n] + W_last[i][1][n])
    // W_last is (32, 2, 10): elem [i][j][n] at i*20 + j*10 + n.
    if (lane < NOUT) {
        float acc = 0.f;
#pragma unroll
        for (int i = 0; i < 32; ++i) {
            float wv = Wl[i*20 + lane] + Wl[i*20 + 10 + lane];
            acc = fmaf(rdp[i], wv, acc);
        }
        zb[w][lane] = acc;
    }
    __syncwarp();
    if (lane < NOUT) {
        float m = -3.402823466e38f;
#pragma unroll
        for (int j = 0; j < NOUT; ++j) m = fmaxf(m, zb[w][j]);
        float s = 0.f;
#pragma unroll
        for (int j = 0; j < NOUT; ++j) s += expf(zb[w][j] - m);
        out[b * NOUT + lane] = zb[w][lane] - m - logf(s);
    }
}

extern "C" void kernel_launch(void* const* d_in, const int* in_sizes, int n_in,
                              void* d_out, int out_size)
{
    const float* x  = (const float*)d_in[0];   // tensor  (batch, 1024)
    const float* Wf = (const float*)d_in[1];   // W_first (1, 2, 32)
    const float* Ws = (const float*)d_in[2];   // W_shared(32, 2, 32)
    const float* Wl = (const float*)d_in[3];   // W_last  (32, 2, 10)
    float* out = (float*)d_out;                // (batch, 10) float32

    int batch  = in_sizes[0] / T_LEN;          // 4096
    int blocks = (batch + 1) / 2;              // 1 row per warp, 2 warps per CTA

    tt_kernel<<<blocks, 64>>>(x, Wf, Ws, Wl, out, batch);
}